// round 5
// baseline (speedup 1.0000x reference)
#include <cuda_runtime.h>
#include <cstdint>

// Problem constants
#define KK   8448
#define NN   25344
#define ZZ   384
#define MM1  1536
#define MM2  16128
#define BW   32          // 1024 batches / 32 bits per word
#define PCMW 48          // 1536 / 32
#define IDXP 1600        // padded index row stride (multiple of 4, >= 1536+32)

// Scratch (device globals — no allocation allowed)
__device__ uint32_t g_u  [(KK + 1) * BW];    // packed u (bits + zero col), [k][w]
__device__ uint32_t g_pa [MM1 * BW];         // packed p_a
__device__ uint32_t g_p1 [(MM1 + 1) * BW];   // packed p1 (+ zero row at MM1)
__device__ uint32_t g_p2 [MM2 * BW];         // packed p2
__device__ uint32_t g_idx[MM1 * IDXP];       // compacted byte-offsets of set bits
__device__ int      g_cnt[MM1];              // padded counts (multiple of 32)

// ---------------------------------------------------------------------------
// 1) Pack bits [B,K] into g_u[k][w]. float4 reads: thread builds 4 words from
//    32 independent 16B loads (high MLP); warp reads 512B contiguous per t.
// ---------------------------------------------------------------------------
__global__ void k_pack_u(const float* __restrict__ bits) {
    int g = blockIdx.x * blockDim.x + threadIdx.x;   // group of 4 k
    int w = blockIdx.y;
    if (g >= KK / 4) return;
    int k = g * 4;

    uint32_t w0 = 0, w1 = 0, w2 = 0, w3 = 0;
    const float4* p = (const float4*)(bits + (size_t)w * 32 * KK + k);
    #pragma unroll 8
    for (int t = 0; t < 32; t++) {
        float4 f = p[(size_t)t * (KK / 4)];
        w0 |= (f.x != 0.0f ? 1u : 0u) << t;
        w1 |= (f.y != 0.0f ? 1u : 0u) << t;
        w2 |= (f.z != 0.0f ? 1u : 0u) << t;
        w3 |= (f.w != 0.0f ? 1u : 0u) << t;
    }
    uint32_t* o = g_u + k * BW + w;
    o[0] = w0; o[BW] = w1; o[2 * BW] = w2; o[3 * BW] = w3;
    if (g == 0) g_u[KK * BW + w] = 0;    // zero column of u
}

// ---------------------------------------------------------------------------
// 2) Fused pcm pack + index compaction. One warp per row: coalesced float
//    reads -> ballot -> compact set-bit positions as pre-scaled byte offsets
//    (j * 128), padded to a multiple of 32 with the zero-row offset.
// ---------------------------------------------------------------------------
__global__ void k_idx(const float* __restrict__ pcm) {
    int row  = blockIdx.x * (blockDim.x >> 5) + (threadIdx.x >> 5);
    int lane = threadIdx.x & 31;
    if (row >= MM1) return;
    const float* pr = pcm + (size_t)row * MM1;
    uint32_t* out = g_idx + row * IDXP;
    int cnt = 0;
    for (int jw = 0; jw < PCMW; jw++) {
        float v = pr[jw * 32 + lane];
        uint32_t bw = __ballot_sync(0xffffffffu, v != 0.0f);
        bool mine = (bw >> lane) & 1u;
        int pos = cnt + __popc(bw & ((1u << lane) - 1u));
        if (mine) out[pos] = (uint32_t)(jw * 32 + lane) << 7;
        cnt += __popc(bw);
    }
    int padded = (cnt + 31) & ~31;
    for (int p = cnt + lane; p < padded; p += 32)
        out[p] = (uint32_t)MM1 << 7;   // points at zeroed smem row
    if (lane == 0) g_cnt[row] = padded;
}

// ---------------------------------------------------------------------------
// 3) p_a[m] = XOR over 19 gathered u rows. Explicit index staging so all 19
//    gathers issue with full MLP.
// ---------------------------------------------------------------------------
__global__ void __launch_bounds__(256) k_pa(const int* __restrict__ ind_a) {
    int tid = blockIdx.x * blockDim.x + threadIdx.x;
    int m = tid >> 5, w = tid & 31;
    if (m >= MM1) return;
    const int* ia = ind_a + m * 19;
    int idx[19];
    #pragma unroll
    for (int j = 0; j < 19; j++) idx[j] = __ldg(ia + j);
    uint32_t acc = 0;
    #pragma unroll
    for (int j = 0; j < 19; j++)
        acc ^= g_u[idx[j] * BW + w];
    g_pa[tid] = acc;
}

// ---------------------------------------------------------------------------
// 4) p1[i] = XOR_{j in idx[i]} p_a[j]. pa staged in smem (+1 zero row).
//    TWO warps per row (alternating 32-chunks). __launch_bounds__(768,1)
//    raises the register budget (~85) so the 8 staged uint4 index loads
//    (32 regs) issue back-to-back -> MLP 8 instead of 2.
// ---------------------------------------------------------------------------
#define P1_ROWS 12
#define P1_THREADS 768                        // 24 warps = 12 row-pairs
#define P1_SMEM (((MM1 + 1) * BW + P1_ROWS * 32) * 4)
__global__ void __launch_bounds__(P1_THREADS, 1) k_p1() {
    extern __shared__ uint32_t pa_sh[];       // (1536+1)*32 words + partials
    uint32_t* part = pa_sh + (MM1 + 1) * BW;  // [12][32]
    int tid = threadIdx.x;

    {   // vectorized preload of g_pa (12288 uint4)
        const uint4* src = (const uint4*)g_pa;
        uint4* dst = (uint4*)pa_sh;
        for (int i = tid; i < MM1 * BW / 4; i += P1_THREADS)
            dst[i] = src[i];
        if (tid < BW) pa_sh[MM1 * BW + tid] = 0;   // zero pad row
    }
    if (blockIdx.x == 0 && tid < BW)
        g_p1[MM1 * BW + tid] = 0;                  // zero row for ind_c2 == M1
    __syncthreads();

    int warp = tid >> 5, lane = tid & 31;
    int r = warp >> 1, half = warp & 1;
    int row = blockIdx.x * P1_ROWS + r;

    const uint4* __restrict__ idxr = (const uint4*)(g_idx + row * IDXP);
    int cnt = g_cnt[row];                          // multiple of 32
    const char* base = (const char*)pa_sh + (lane << 2);

    uint32_t a0 = 0, a1 = 0, a2 = 0, a3 = 0;
    for (int c = half * 32; c < cnt; c += 64) {
        const uint4* q = idxr + (c >> 2);
        uint4 o[8];
        #pragma unroll
        for (int s = 0; s < 8; s++)                // 8 independent 16B LDGs
            o[s] = __ldg(q + s);
        #pragma unroll
        for (int s = 0; s < 8; s++) {
            a0 ^= *(const uint32_t*)(base + o[s].x);
            a1 ^= *(const uint32_t*)(base + o[s].y);
            a2 ^= *(const uint32_t*)(base + o[s].z);
            a3 ^= *(const uint32_t*)(base + o[s].w);
        }
    }
    uint32_t acc = a0 ^ a1 ^ a2 ^ a3;
    if (half) part[r * 32 + lane] = acc;
    __syncthreads();
    if (!half) g_p1[row * BW + lane] = acc ^ part[r * 32 + lane];
}

// ---------------------------------------------------------------------------
// 5) p2[m] = XOR of 6 u-gathers + 4 p1e-gathers. Lanes = w -> every gather is
//    one coalesced 128B warp-load. Indices staged for MLP.
// ---------------------------------------------------------------------------
__global__ void __launch_bounds__(256) k_p2(const int* __restrict__ ind_c1,
                                            const int* __restrict__ ind_c2) {
    int tid = blockIdx.x * blockDim.x + threadIdx.x;
    int m = tid >> 5, w = tid & 31;
    if (m >= MM2) return;
    const int* c1 = ind_c1 + m * 6;
    const int* c2 = ind_c2 + m * 4;
    int i1[6], i2[4];
    #pragma unroll
    for (int j = 0; j < 6; j++) i1[j] = __ldg(c1 + j);
    #pragma unroll
    for (int j = 0; j < 4; j++) i2[j] = __ldg(c2 + j);
    uint32_t acc = 0;
    #pragma unroll
    for (int j = 0; j < 6; j++) acc ^= g_u [i1[j] * BW + w];
    #pragma unroll
    for (int j = 0; j < 4; j++) acc ^= g_p1[i2[j] * BW + w];
    g_p2[tid] = acc;
}

// ---------------------------------------------------------------------------
// 6) Output: out[b][n] = bit of c_full[out_int[n] + 2Z], b = w*32 + t.
//    Thread handles 4 consecutive n -> streaming float4 stores.
// ---------------------------------------------------------------------------
__global__ void k_out(const int* __restrict__ oint, float* __restrict__ out) {
    int g = blockIdx.x * blockDim.x + threadIdx.x;  // group of 4 n
    int w = blockIdx.y;
    if (g >= NN / 4) return;
    int n = g * 4;

    uint32_t wd[4];
    #pragma unroll
    for (int q = 0; q < 4; q++) {
        int src = __ldg(oint + n + q) + 2 * ZZ;
        uint32_t v;
        if (src < KK)            v = g_u [src * BW + w];
        else if (src < KK + MM1) v = g_p1[(src - KK) * BW + w];
        else                     v = g_p2[(src - KK - MM1) * BW + w];
        wd[q] = v;
    }

    float4* ob = (float4*)(out + (size_t)w * 32 * NN + n);
    #pragma unroll 8
    for (int t = 0; t < 32; t++) {
        float4 f;
        f.x = (float)((wd[0] >> t) & 1u);
        f.y = (float)((wd[1] >> t) & 1u);
        f.z = (float)((wd[2] >> t) & 1u);
        f.w = (float)((wd[3] >> t) & 1u);
        __stcs(&ob[(size_t)t * (NN / 4)], f);
    }
}

// ---------------------------------------------------------------------------
extern "C" void kernel_launch(void* const* d_in, const int* in_sizes, int n_in,
                              void* d_out, int out_size) {
    const float* bits   = (const float*)d_in[0];
    const float* pcm    = (const float*)d_in[1];
    const int*   ind_a  = (const int*)  d_in[2];
    const int*   ind_c1 = (const int*)  d_in[3];
    const int*   ind_c2 = (const int*)  d_in[4];
    const int*   oint   = (const int*)  d_in[5];
    float* out = (float*)d_out;

    cudaFuncSetAttribute(k_p1, cudaFuncAttributeMaxDynamicSharedMemorySize,
                         P1_SMEM);

    k_pack_u<<<dim3((KK / 4 + 255) / 256, 32), 256>>>(bits);
    k_idx   <<<MM1 / 8, 256>>>(pcm);
    k_pa    <<<(MM1 * 32) / 256, 256>>>(ind_a);
    k_p1    <<<128, P1_THREADS, P1_SMEM>>>();
    k_p2    <<<(MM2 * 32 + 255) / 256, 256>>>(ind_c1, ind_c2);
    k_out   <<<dim3((NN / 4 + 255) / 256, 32), 256>>>(oint, out);
}

// round 6
// speedup vs baseline: 1.0005x; 1.0005x over previous
#include <cuda_runtime.h>
#include <cstdint>

// Problem constants
#define KK   8448
#define NN   25344
#define ZZ   384
#define MM1  1536
#define MM2  16128
#define BW   32          // 1024 batches / 32 bits per word
#define PCMW 48          // 1536 / 32
#define IDXP 1600        // padded index row stride (multiple of 4, >= 1536+32)

// Scratch (device globals — no allocation allowed)
__device__ uint32_t g_u  [(KK + 1) * BW];    // packed u (bits + zero col), [k][w]
__device__ uint32_t g_pa [MM1 * BW];         // packed p_a
__device__ uint32_t g_p1 [(MM1 + 1) * BW];   // packed p1 (+ zero row at MM1)
__device__ uint32_t g_p2 [MM2 * BW];         // packed p2
__device__ uint32_t g_idx[MM1 * IDXP];       // compacted byte-offsets of set bits
__device__ int      g_cnt[MM1];              // padded counts (multiple of 32)

// ---------------------------------------------------------------------------
// 1) Pack bits [B,K] into g_u[k][w]. float4 reads: thread builds 4 words from
//    32 independent 16B loads (high MLP); warp reads 512B contiguous per t.
// ---------------------------------------------------------------------------
__global__ void k_pack_u(const float* __restrict__ bits) {
    int g = blockIdx.x * blockDim.x + threadIdx.x;   // group of 4 k
    int w = blockIdx.y;
    if (g >= KK / 4) return;
    int k = g * 4;

    uint32_t w0 = 0, w1 = 0, w2 = 0, w3 = 0;
    const float4* p = (const float4*)(bits + (size_t)w * 32 * KK + k);
    #pragma unroll 8
    for (int t = 0; t < 32; t++) {
        float4 f = p[(size_t)t * (KK / 4)];
        w0 |= (f.x != 0.0f ? 1u : 0u) << t;
        w1 |= (f.y != 0.0f ? 1u : 0u) << t;
        w2 |= (f.z != 0.0f ? 1u : 0u) << t;
        w3 |= (f.w != 0.0f ? 1u : 0u) << t;
    }
    uint32_t* o = g_u + k * BW + w;
    o[0] = w0; o[BW] = w1; o[2 * BW] = w2; o[3 * BW] = w3;
    if (g == 0) g_u[KK * BW + w] = 0;    // zero column of u
}

// ---------------------------------------------------------------------------
// 2) Fused pcm pack + index compaction. One warp per row: coalesced float
//    reads -> ballot -> compact set-bit positions as pre-scaled byte offsets
//    (j * 128), padded to a multiple of 32 with the zero-row offset.
// ---------------------------------------------------------------------------
__global__ void k_idx(const float* __restrict__ pcm) {
    int row  = blockIdx.x * (blockDim.x >> 5) + (threadIdx.x >> 5);
    int lane = threadIdx.x & 31;
    if (row >= MM1) return;
    const float* pr = pcm + (size_t)row * MM1;
    uint32_t* out = g_idx + row * IDXP;
    int cnt = 0;
    for (int jw = 0; jw < PCMW; jw++) {
        float v = pr[jw * 32 + lane];
        uint32_t bw = __ballot_sync(0xffffffffu, v != 0.0f);
        bool mine = (bw >> lane) & 1u;
        int pos = cnt + __popc(bw & ((1u << lane) - 1u));
        if (mine) out[pos] = (uint32_t)(jw * 32 + lane) << 7;
        cnt += __popc(bw);
    }
    int padded = (cnt + 31) & ~31;
    for (int p = cnt + lane; p < padded; p += 32)
        out[p] = (uint32_t)MM1 << 7;   // points at zeroed smem row
    if (lane == 0) g_cnt[row] = padded;
}

// ---------------------------------------------------------------------------
// 3) p_a[m] = XOR over 19 gathered u rows. Explicit index staging so all 19
//    gathers issue with full MLP.
// ---------------------------------------------------------------------------
__global__ void __launch_bounds__(256) k_pa(const int* __restrict__ ind_a) {
    int tid = blockIdx.x * blockDim.x + threadIdx.x;
    int m = tid >> 5, w = tid & 31;
    if (m >= MM1) return;
    const int* ia = ind_a + m * 19;
    int idx[19];
    #pragma unroll
    for (int j = 0; j < 19; j++) idx[j] = __ldg(ia + j);
    uint32_t acc = 0;
    #pragma unroll
    for (int j = 0; j < 19; j++)
        acc ^= g_u[idx[j] * BW + w];
    g_pa[tid] = acc;
}

// ---------------------------------------------------------------------------
// 4) p1[i] = XOR_{j in idx[i]} p_a[j]. pa staged in smem (+1 zero row).
//    TWO warps per row (alternating 32-chunks). __launch_bounds__(768,1)
//    raises the register budget (~85) so the 8 staged uint4 index loads
//    (32 regs) issue back-to-back -> MLP 8 instead of 2.
// ---------------------------------------------------------------------------
#define P1_ROWS 12
#define P1_THREADS 768                        // 24 warps = 12 row-pairs
#define P1_SMEM (((MM1 + 1) * BW + P1_ROWS * 32) * 4)
__global__ void __launch_bounds__(P1_THREADS, 1) k_p1() {
    extern __shared__ uint32_t pa_sh[];       // (1536+1)*32 words + partials
    uint32_t* part = pa_sh + (MM1 + 1) * BW;  // [12][32]
    int tid = threadIdx.x;

    {   // vectorized preload of g_pa (12288 uint4)
        const uint4* src = (const uint4*)g_pa;
        uint4* dst = (uint4*)pa_sh;
        for (int i = tid; i < MM1 * BW / 4; i += P1_THREADS)
            dst[i] = src[i];
        if (tid < BW) pa_sh[MM1 * BW + tid] = 0;   // zero pad row
    }
    if (blockIdx.x == 0 && tid < BW)
        g_p1[MM1 * BW + tid] = 0;                  // zero row for ind_c2 == M1
    __syncthreads();

    int warp = tid >> 5, lane = tid & 31;
    int r = warp >> 1, half = warp & 1;
    int row = blockIdx.x * P1_ROWS + r;

    const uint4* __restrict__ idxr = (const uint4*)(g_idx + row * IDXP);
    int cnt = g_cnt[row];                          // multiple of 32
    const char* base = (const char*)pa_sh + (lane << 2);

    uint32_t a0 = 0, a1 = 0, a2 = 0, a3 = 0;
    for (int c = half * 32; c < cnt; c += 64) {
        const uint4* q = idxr + (c >> 2);
        uint4 o[8];
        #pragma unroll
        for (int s = 0; s < 8; s++)                // 8 independent 16B LDGs
            o[s] = __ldg(q + s);
        #pragma unroll
        for (int s = 0; s < 8; s++) {
            a0 ^= *(const uint32_t*)(base + o[s].x);
            a1 ^= *(const uint32_t*)(base + o[s].y);
            a2 ^= *(const uint32_t*)(base + o[s].z);
            a3 ^= *(const uint32_t*)(base + o[s].w);
        }
    }
    uint32_t acc = a0 ^ a1 ^ a2 ^ a3;
    if (half) part[r * 32 + lane] = acc;
    __syncthreads();
    if (!half) g_p1[row * BW + lane] = acc ^ part[r * 32 + lane];
}

// ---------------------------------------------------------------------------
// 5) p2[m] = XOR of 6 u-gathers + 4 p1e-gathers. Lanes = w -> every gather is
//    one coalesced 128B warp-load. Indices staged for MLP.
// ---------------------------------------------------------------------------
__global__ void __launch_bounds__(256) k_p2(const int* __restrict__ ind_c1,
                                            const int* __restrict__ ind_c2) {
    int tid = blockIdx.x * blockDim.x + threadIdx.x;
    int m = tid >> 5, w = tid & 31;
    if (m >= MM2) return;
    const int* c1 = ind_c1 + m * 6;
    const int* c2 = ind_c2 + m * 4;
    int i1[6], i2[4];
    #pragma unroll
    for (int j = 0; j < 6; j++) i1[j] = __ldg(c1 + j);
    #pragma unroll
    for (int j = 0; j < 4; j++) i2[j] = __ldg(c2 + j);
    uint32_t acc = 0;
    #pragma unroll
    for (int j = 0; j < 6; j++) acc ^= g_u [i1[j] * BW + w];
    #pragma unroll
    for (int j = 0; j < 4; j++) acc ^= g_p1[i2[j] * BW + w];
    g_p2[tid] = acc;
}

// ---------------------------------------------------------------------------
// 6) Output: out[b][n] = bit of c_full[out_int[n] + 2Z], b = w*32 + t.
//    Thread handles 4 consecutive n -> streaming float4 stores.
// ---------------------------------------------------------------------------
__global__ void k_out(const int* __restrict__ oint, float* __restrict__ out) {
    int g = blockIdx.x * blockDim.x + threadIdx.x;  // group of 4 n
    int w = blockIdx.y;
    if (g >= NN / 4) return;
    int n = g * 4;

    uint32_t wd[4];
    #pragma unroll
    for (int q = 0; q < 4; q++) {
        int src = __ldg(oint + n + q) + 2 * ZZ;
        uint32_t v;
        if (src < KK)            v = g_u [src * BW + w];
        else if (src < KK + MM1) v = g_p1[(src - KK) * BW + w];
        else                     v = g_p2[(src - KK - MM1) * BW + w];
        wd[q] = v;
    }

    float4* ob = (float4*)(out + (size_t)w * 32 * NN + n);
    #pragma unroll 8
    for (int t = 0; t < 32; t++) {
        float4 f;
        f.x = (float)((wd[0] >> t) & 1u);
        f.y = (float)((wd[1] >> t) & 1u);
        f.z = (float)((wd[2] >> t) & 1u);
        f.w = (float)((wd[3] >> t) & 1u);
        __stcs(&ob[(size_t)t * (NN / 4)], f);
    }
}

// ---------------------------------------------------------------------------
extern "C" void kernel_launch(void* const* d_in, const int* in_sizes, int n_in,
                              void* d_out, int out_size) {
    const float* bits   = (const float*)d_in[0];
    const float* pcm    = (const float*)d_in[1];
    const int*   ind_a  = (const int*)  d_in[2];
    const int*   ind_c1 = (const int*)  d_in[3];
    const int*   ind_c2 = (const int*)  d_in[4];
    const int*   oint   = (const int*)  d_in[5];
    float* out = (float*)d_out;

    cudaFuncSetAttribute(k_p1, cudaFuncAttributeMaxDynamicSharedMemorySize,
                         P1_SMEM);

    k_pack_u<<<dim3((KK / 4 + 255) / 256, 32), 256>>>(bits);
    k_idx   <<<MM1 / 8, 256>>>(pcm);
    k_pa    <<<(MM1 * 32) / 256, 256>>>(ind_a);
    k_p1    <<<128, P1_THREADS, P1_SMEM>>>();
    k_p2    <<<(MM2 * 32 + 255) / 256, 256>>>(ind_c1, ind_c2);
    k_out   <<<dim3((NN / 4 + 255) / 256, 32), 256>>>(oint, out);
}